// round 1
// baseline (speedup 1.0000x reference)
#include <cuda_runtime.h>
#include <math.h>

// ---------------------------------------------------------------------------
// RegionLoss (YOLO-style) for fixed shapes:
//   output : (16, 5*(7+8)=75, 96, 96) float32
//   target : (16, 50, 7)              float32
//   anchors: (10,)                    float32
// returns (loss, nCorrect, nGT) as 3 float32 scalars.
// ---------------------------------------------------------------------------

#define NB   16
#define NANC 5
#define NCL  8
#define NT   50
#define NH   96
#define NW   96
#define HW   (NH * NW)            // 9216
#define CELLS_PER_B (NANC * HW)   // 46080
#define NTOT (NB * CELLS_PER_B)   // 737280
#define NBT  (NB * NT)            // 800
#define NCHAN (7 + NCL)           // 15

#define THRESH_Q 0.375f           // 0.6/(1+0.6): iou>0.6 <=> inter > 0.375*(ap+ag)
#define OBJW 10.0f

// -------------------- device scratch (no allocations allowed) ---------------
__device__ float4 g_box[NBT];     // {gx_lo, gx_hi, gy_lo, gy_hi}, inverted if invalid
__device__ float  g_thr[NBT];     // 0.375 * gw * gl
__device__ int    g_widx[NBT];    // winner cell index (linear in N) or -1
__device__ float  g_tx[NBT], g_ty[NBT], g_tw[NBT], g_tl[NBT];
__device__ float  g_tim[NBT], g_tre[NBT], g_tconf[NBT];
__device__ int    g_tcls[NBT];
__device__ double g_loss;
__device__ int    g_nGT, g_nCorrect;

__device__ __forceinline__ float sig_fast(float x) {
    return 1.0f / (1.0f + __expf(-x));
}
__device__ __forceinline__ float sig_acc(float x) {
    return 1.0f / (1.0f + expf(-x));
}

// -------------------- kernel 0: zero accumulators ----------------------------
__global__ void k_init() {
    g_loss = 0.0;
    g_nGT = 0;
    g_nCorrect = 0;
}

// -------------------- kernel 1: per-target preparation -----------------------
// grid = NB blocks, 64 threads (t < NT active)
__global__ void k_targets(const float* __restrict__ out,
                          const float* __restrict__ tgt,
                          const float* __restrict__ anc) {
    const int b = blockIdx.x;
    const int t = threadIdx.x;

    __shared__ int s_idx[NT];

    bool valid = false;
    float gx = 0.f, gy = 0.f, gw = 1.f, gl = 1.f;
    int bn = 0, gi = 0, gj = 0, idx = -2;

    if (t < NT) {
        // valid = cumprod(target[:, :, 1] != 0) up to t
        valid = true;
        for (int k = 0; k <= t; k++) {
            valid = valid && (tgt[(b * NT + k) * 7 + 1] != 0.0f);
        }
        const float* tp = tgt + (b * NT + t) * 7;
        gx = tp[1] * (float)NW;
        gy = tp[2] * (float)NH;
        gw = tp[3] * (float)NW;
        gl = tp[4] * (float)NH;

        // best anchor (argmax anc_iou, ties -> first)
        float best = -1.0f;
        #pragma unroll
        for (int i = 0; i < NANC; i++) {
            float aw_ = __ldg(anc + 2 * i);
            float ah_ = __ldg(anc + 2 * i + 1);
            float inter = fminf(gw, aw_) * fminf(gl, ah_);
            float iou = inter / ((gw * gl + aw_ * ah_) - inter);
            if (iou > best) { best = iou; bn = i; }
        }
        gi = min(max((int)gx, 0), NW - 1);
        gj = min(max((int)gy, 0), NH - 1);
        idx = ((b * NANC + bn) * NH + gj) * NW + gi;
        s_idx[t] = valid ? idx : (-2 - t);   // invalid: unique, never matches
    }
    __syncthreads();

    if (t >= NT) return;

    const int g = b * NT + t;

    // winner = valid and no later valid target with same idx (last write wins)
    bool winner = valid;
    if (valid) {
        for (int t2 = t + 1; t2 < NT; t2++) {
            if (s_idx[t2] == idx) winner = false;
        }
    }

    if (valid) {
        g_box[g] = make_float4(gx - 0.5f * gw, gx + 0.5f * gw,
                               gy - 0.5f * gl, gy + 0.5f * gl);
        g_thr[g] = THRESH_Q * gw * gl;
    } else {
        g_box[g] = make_float4(1e30f, -1e30f, 1e30f, -1e30f);  // no overlap ever
        g_thr[g] = 0.0f;
    }
    g_widx[g] = winner ? idx : -1;

    if (valid) {
        float aw_ = __ldg(anc + 2 * bn);
        float ah_ = __ldg(anc + 2 * bn + 1);

        // gather pred box at this cell (accurate math: feeds nCorrect & tconf)
        size_t base = (size_t)(b * (NANC * NCHAN) + bn * NCHAN) * HW + (size_t)gj * NW + gi;
        float xr = out[base];
        float yr = out[base + HW];
        float wr = out[base + 2 * HW];
        float lr = out[base + 3 * HW];
        float px = sig_acc(xr) + (float)gi;
        float py = sig_acc(yr) + (float)gj;
        float pw = expf(wr) * aw_;
        float pl = expf(lr) * ah_;

        // replicate reference _iou_xywh arithmetic exactly
        float mx = fminf(px - pw * 0.5f, gx - gw * 0.5f);
        float Mx = fmaxf(px + pw * 0.5f, gx + gw * 0.5f);
        float my = fminf(py - pl * 0.5f, gy - gl * 0.5f);
        float My = fmaxf(py + pl * 0.5f, gy + gl * 0.5f);
        float cw = (pw + gw) - (Mx - mx);
        float ch = (pl + gl) - (My - my);
        float inter = ((cw > 0.f) && (ch > 0.f)) ? (cw * ch) : 0.0f;
        float iou = inter / ((pw * pl + gw * gl) - inter);

        atomicAdd(&g_nGT, 1);
        if (iou > 0.5f) atomicAdd(&g_nCorrect, 1);

        if (winner) {
            const float* tp = tgt + (b * NT + t) * 7;
            g_tx[g] = gx - (float)gi;
            g_ty[g] = gy - (float)gj;
            g_tw[g] = logf(gw / aw_);
            g_tl[g] = logf(gl / ah_);
            g_tim[g] = tp[5];
            g_tre[g] = tp[6];
            g_tcls[g] = (int)tp[0];
            g_tconf[g] = iou;
        }
    }
}

// -------------------- target-cell loss terms (rare path, <=800 cells) -------
__device__ float target_terms(int g, float sx, float sy, float wv, float lv,
                              float imv, float rev, float cf,
                              const float* __restrict__ base, int off) {
    float dx = sx - g_tx[g];
    float dy = sy - g_ty[g];
    float dw = wv - g_tw[g];
    float dl = lv - g_tl[g];
    float di = imv - g_tim[g];
    float dr = rev - g_tre[g];
    float dc = cf - g_tconf[g];

    // cross-entropy over 8 class logits (channels 7..14)
    float lg[NCL];
    #pragma unroll
    for (int c = 0; c < NCL; c++) lg[c] = base[(7 + c) * HW + off];
    float m = lg[0];
    #pragma unroll
    for (int c = 1; c < NCL; c++) m = fmaxf(m, lg[c]);
    float s = 0.f;
    #pragma unroll
    for (int c = 0; c < NCL; c++) s += expf(lg[c] - m);
    float lse = m + logf(s);
    float ce = lse - lg[g_tcls[g]];

    return dx * dx + dy * dy + dw * dw + dl * dl + di * di + dr * dr
         + 100.0f * dc * dc + ce;
}

// -------------------- kernel 2: main per-cell pass ---------------------------
// 2 cells per thread along W. grid = (90, 16), block = 256.
__global__ void __launch_bounds__(256)
k_main(const float* __restrict__ out, const float* __restrict__ anc) {
    const int b = blockIdx.y;
    const int tid = threadIdx.x;

    __shared__ float4 s_box[NT];
    __shared__ float  s_thr[NT];
    __shared__ int    s_widx[NT];
    __shared__ float  s_anch[2 * NANC];

    if (tid < NT) {
        int g = b * NT + tid;
        s_box[tid]  = g_box[g];
        s_thr[tid]  = g_thr[g];
        s_widx[tid] = g_widx[g];
    }
    if (tid < 2 * NANC) s_anch[tid] = anc[tid];
    __syncthreads();

    const int i = blockIdx.x * 256 + tid;   // [0, 23040)
    const int u = i * 2;                    // even cell index within batch b
    const int a = u / HW;
    const int rem = u - a * HW;
    const int h = rem / NW;
    const int w0 = rem - h * NW;

    const float* base = out + (size_t)(b * (NANC * NCHAN) + a * NCHAN) * HW + rem;

    float2 xr  = *(const float2*)(base);
    float2 yr  = *(const float2*)(base + HW);
    float2 wr  = *(const float2*)(base + 2 * HW);
    float2 lr  = *(const float2*)(base + 3 * HW);
    float2 imr = *(const float2*)(base + 4 * HW);
    float2 rer = *(const float2*)(base + 5 * HW);
    float2 cfr = *(const float2*)(base + 6 * HW);

    const float aw_ = s_anch[2 * a];
    const float ah_ = s_anch[2 * a + 1];

    float sx0 = sig_fast(xr.x), sx1 = sig_fast(xr.y);
    float sy0 = sig_fast(yr.x), sy1 = sig_fast(yr.y);
    float pw0 = __expf(wr.x) * aw_, pw1 = __expf(wr.y) * aw_;
    float pl0 = __expf(lr.x) * ah_, pl1 = __expf(lr.y) * ah_;

    float px0 = sx0 + (float)w0, px1 = sx1 + (float)(w0 + 1);
    float py0 = sy0 + (float)h,  py1 = sy1 + (float)h;

    float xlo0 = px0 - 0.5f * pw0, xhi0 = px0 + 0.5f * pw0;
    float ylo0 = py0 - 0.5f * pl0, yhi0 = py0 + 0.5f * pl0;
    float xlo1 = px1 - 0.5f * pw1, xhi1 = px1 + 0.5f * pw1;
    float ylo1 = py1 - 0.5f * pl1, yhi1 = py1 + 0.5f * pl1;
    float ap0 = THRESH_Q * pw0 * pl0;
    float ap1 = THRESH_Q * pw1 * pl1;

    const int cid0 = b * CELLS_PER_B + u;
    const int cid1 = cid0 + 1;

    bool f0 = false, f1 = false;
    int mt0 = -1, mt1 = -1;

    #pragma unroll 10
    for (int t = 0; t < NT; t++) {
        float4 bx = s_box[t];
        float th = s_thr[t];
        int wi = s_widx[t];

        float cw0 = fminf(xhi0, bx.y) - fmaxf(xlo0, bx.x);
        float ch0 = fminf(yhi0, bx.w) - fmaxf(ylo0, bx.z);
        f0 = f0 | ((cw0 > 0.f) & (ch0 > 0.f) & (cw0 * ch0 > th + ap0));

        float cw1 = fminf(xhi1, bx.y) - fmaxf(xlo1, bx.x);
        float ch1 = fminf(yhi1, bx.w) - fmaxf(ylo1, bx.z);
        f1 = f1 | ((cw1 > 0.f) & (ch1 > 0.f) & (cw1 * ch1 > th + ap1));

        if (wi == cid0) mt0 = t;
        if (wi == cid1) mt1 = t;
    }

    float cf0 = sig_fast(cfr.x);
    float cf1 = sig_fast(cfr.y);

    float part = 0.0f;
    if (mt0 >= 0) {
        part += target_terms(b * NT + mt0, sx0, sy0, wr.x, lr.x, imr.x, rer.x, cf0, base, 0);
    } else if (!f0) {
        part += cf0 * cf0;     // conf_mask = NOOBJ = 1, tconf = 0
    }
    if (mt1 >= 0) {
        part += target_terms(b * NT + mt1, sx1, sy1, wr.y, lr.y, imr.y, rer.y, cf1, base, 1);
    } else if (!f1) {
        part += cf1 * cf1;
    }

    // block reduction -> one double atomic per block
    __shared__ float red[256];
    red[tid] = part;
    __syncthreads();
    #pragma unroll
    for (int s = 128; s > 0; s >>= 1) {
        if (tid < s) red[tid] += red[tid + s];
        __syncthreads();
    }
    if (tid == 0) atomicAdd(&g_loss, (double)red[0]);
}

// -------------------- kernel 3: finalize -------------------------------------
__global__ void k_fin(float* __restrict__ o, int n) {
    if (n > 0) o[0] = (float)g_loss;
    if (n > 1) o[1] = (float)g_nCorrect;
    if (n > 2) o[2] = (float)g_nGT;
    for (int k = 3; k < n; k++) o[k] = 0.0f;
}

// -------------------- launch ------------------------------------------------
extern "C" void kernel_launch(void* const* d_in, const int* in_sizes, int n_in,
                              void* d_out, int out_size) {
    const float* output  = (const float*)d_in[0];
    const float* target  = (const float*)d_in[1];
    const float* anchors = (const float*)d_in[2];

    k_init<<<1, 1>>>();
    k_targets<<<NB, 64>>>(output, target, anchors);
    k_main<<<dim3((CELLS_PER_B / 2 + 255) / 256, NB), 256>>>(output, anchors);
    k_fin<<<1, 1>>>((float*)d_out, out_size);
}

// round 3
// speedup vs baseline: 1.4015x; 1.4015x over previous
#include <cuda_runtime.h>
#include <math.h>

// ---------------------------------------------------------------------------
// RegionLoss (YOLO-style), fixed shapes:
//   output : (16, 75, 96, 96) f32, target: (16, 50, 7) f32, anchors: (10,) f32
// out: (loss, nCorrect, nGT) f32
// ---------------------------------------------------------------------------

#define NB   16
#define NANC 5
#define NCL  8
#define NT   50
#define NH   96
#define NW   96
#define HW   (NH * NW)            // 9216
#define CELLS_PER_B (NANC * HW)   // 46080
#define NTOT (NB * CELLS_PER_B)   // 737280
#define NBT  (NB * NT)            // 800
#define BLKS_PER_B 45             // 46080 / (256 threads * 4 cells)
#define NBLK (NB * BLKS_PER_B)    // 720

#define THRESH_Q 0.375f           // iou>0.6 <=> inter > 0.375*(areaP+areaG)

// -------------------- device scratch (no allocations allowed) ---------------
__device__ float4 g_box[NBT];     // {xlo, xhi, ylo, yhi}; inverted if invalid
__device__ float  g_thr[NBT];     // 0.375*gw*gl (1e30 if invalid)
__device__ int    g_widx[NBT];    // winner cell index or -1
__device__ float  g_tx[NBT], g_ty[NBT], g_tw[NBT], g_tl[NBT];
__device__ float  g_tim[NBT], g_tre[NBT], g_tconf[NBT];
__device__ int    g_tcls[NBT];
__device__ unsigned char g_match[NTOT];   // t+1 at winner cells, else 0 (zero-init; restored by k_fin)
__device__ float  g_part[NBLK];           // per-block loss partials
__device__ int    g_cntGT[NB], g_cntCor[NB];

__device__ __forceinline__ float sig_fast(float x) { return 1.0f / (1.0f + __expf(-x)); }
__device__ __forceinline__ float sig_acc(float x)  { return 1.0f / (1.0f + expf(-x)); }

// -------------------- kernel 1: per-target prep -------------------------------
// grid = NB, block = 64 (t < NT active)
__global__ void k_targets(const float* __restrict__ out,
                          const float* __restrict__ tgt,
                          const float* __restrict__ anc) {
    const int b = blockIdx.x;
    const int t = threadIdx.x;

    __shared__ float s_t1[NT];
    __shared__ int   s_idx[NT];
    __shared__ int   s_v[NT], s_c[NT];

    if (t < NT) s_t1[t] = tgt[(b * NT + t) * 7 + 1];
    __syncthreads();

    bool valid = false;
    float gx = 0.f, gy = 0.f, gw = 1.f, gl = 1.f;
    int bn = 0, gi = 0, gj = 0, idx = -2;

    if (t < NT) {
        valid = true;
        for (int k = 0; k <= t; k++) valid = valid && (s_t1[k] != 0.0f);

        const float* tp = tgt + (b * NT + t) * 7;
        gx = tp[1] * (float)NW;
        gy = tp[2] * (float)NH;
        gw = tp[3] * (float)NW;
        gl = tp[4] * (float)NH;

        float best = -1.0f;
        #pragma unroll
        for (int i = 0; i < NANC; i++) {
            float aw_ = __ldg(anc + 2 * i);
            float ah_ = __ldg(anc + 2 * i + 1);
            float inter = fminf(gw, aw_) * fminf(gl, ah_);
            float iou = inter / ((gw * gl + aw_ * ah_) - inter);
            if (iou > best) { best = iou; bn = i; }
        }
        gi = min(max((int)gx, 0), NW - 1);
        gj = min(max((int)gy, 0), NH - 1);
        idx = ((b * NANC + bn) * NH + gj) * NW + gi;
        s_idx[t] = valid ? idx : (-2 - t);
    }
    __syncthreads();

    bool corr = false;

    if (t < NT) {
        const int g = b * NT + t;

        bool winner = valid;
        if (valid) {
            for (int t2 = t + 1; t2 < NT; t2++)
                if (s_idx[t2] == idx) winner = false;
        }

        if (valid) {
            g_box[g] = make_float4(gx - 0.5f * gw, gx + 0.5f * gw,
                                   gy - 0.5f * gl, gy + 0.5f * gl);
            g_thr[g] = THRESH_Q * gw * gl;
        } else {
            g_box[g] = make_float4(1e30f, -1e30f, 1e30f, -1e30f);
            g_thr[g] = 1e30f;
        }
        g_widx[g] = winner ? idx : -1;

        if (valid) {
            float aw_ = __ldg(anc + 2 * bn);
            float ah_ = __ldg(anc + 2 * bn + 1);

            size_t base = (size_t)(b * (NANC * 15) + bn * 15) * HW + (size_t)gj * NW + gi;
            float px = sig_acc(out[base])        + (float)gi;
            float py = sig_acc(out[base + HW])   + (float)gj;
            float pw = expf(out[base + 2 * HW]) * aw_;
            float pl = expf(out[base + 3 * HW]) * ah_;

            // reference _iou_xywh arithmetic exactly (feeds nCorrect & tconf)
            float mx = fminf(px - pw * 0.5f, gx - gw * 0.5f);
            float Mx = fmaxf(px + pw * 0.5f, gx + gw * 0.5f);
            float my = fminf(py - pl * 0.5f, gy - gl * 0.5f);
            float My = fmaxf(py + pl * 0.5f, gy + gl * 0.5f);
            float cw = (pw + gw) - (Mx - mx);
            float ch = (pl + gl) - (My - my);
            float inter = ((cw > 0.f) && (ch > 0.f)) ? (cw * ch) : 0.0f;
            float iou = inter / ((pw * pl + gw * gl) - inter);
            corr = (iou > 0.5f);

            if (winner) {
                const float* tp = tgt + (b * NT + t) * 7;
                g_tx[g]    = gx - (float)gi;
                g_ty[g]    = gy - (float)gj;
                g_tw[g]    = logf(gw / aw_);
                g_tl[g]    = logf(gl / ah_);
                g_tim[g]   = tp[5];
                g_tre[g]   = tp[6];
                g_tcls[g]  = (int)tp[0];
                g_tconf[g] = iou;
                g_match[idx] = (unsigned char)(t + 1);
            }
        }
        s_v[t] = valid ? 1 : 0;
        s_c[t] = corr ? 1 : 0;
    }
    __syncthreads();

    if (t == 0) {
        int sv = 0, sc = 0;
        for (int k = 0; k < NT; k++) { sv += s_v[k]; sc += s_c[k]; }
        g_cntGT[b]  = sv;
        g_cntCor[b] = sc;
    }
}

// -------------------- matched-cell loss terms (<=800 cells) ------------------
__device__ __noinline__ float target_terms(int g, float sx, float sy, float wv, float lv,
                                           float cf, const float* __restrict__ base, int off) {
    float dx = sx - g_tx[g];
    float dy = sy - g_ty[g];
    float dw = wv - g_tw[g];
    float dl = lv - g_tl[g];
    float di = base[4 * HW + off] - g_tim[g];
    float dr = base[5 * HW + off] - g_tre[g];
    float dc = cf - g_tconf[g];

    float lg[NCL];
    #pragma unroll
    for (int c = 0; c < NCL; c++) lg[c] = base[(7 + c) * HW + off];
    float m = lg[0];
    #pragma unroll
    for (int c = 1; c < NCL; c++) m = fmaxf(m, lg[c]);
    float s = 0.f;
    #pragma unroll
    for (int c = 0; c < NCL; c++) s += expf(lg[c] - m);
    float ce = (m + logf(s)) - lg[g_tcls[g]];

    return dx * dx + dy * dy + dw * dw + dl * dl + di * di + dr * dr
         + 100.0f * dc * dc + ce;
}

// -------------------- kernel 2: main per-cell pass ----------------------------
// 4 cells/thread. grid = (45, 16), block = 256.
__global__ void __launch_bounds__(256)
k_main(const float* __restrict__ out, const float* __restrict__ anc) {
    const int b   = blockIdx.y;
    const int tid = threadIdx.x;

    __shared__ float4 s_box[NT];
    __shared__ float  s_thr[NT];
    if (tid < NT) {
        s_box[tid] = g_box[b * NT + tid];
        s_thr[tid] = g_thr[b * NT + tid];
    }
    __syncthreads();

    const int u   = blockIdx.x * 1024 + tid * 4;   // cell index within batch
    const int a   = u / HW;
    const int rem = u - a * HW;
    const int h   = rem / NW;
    const int w0  = rem - h * NW;

    const float* base = out + (size_t)(b * 75 + a * 15) * HW + rem;

    const float4 xr  = *(const float4*)(base);
    const float4 yr  = *(const float4*)(base + HW);
    const float4 wr  = *(const float4*)(base + 2 * HW);
    const float4 lr  = *(const float4*)(base + 3 * HW);
    const float4 cfr = *(const float4*)(base + 6 * HW);
    const uchar4 mk  = *(const uchar4*)(g_match + b * CELLS_PER_B + u);

    const float aw_ = __ldg(anc + 2 * a);
    const float ah_ = __ldg(anc + 2 * a + 1);

    const float X[4] = {xr.x, xr.y, xr.z, xr.w};
    const float Y[4] = {yr.x, yr.y, yr.z, yr.w};
    const float W[4] = {wr.x, wr.y, wr.z, wr.w};
    const float L[4] = {lr.x, lr.y, lr.z, lr.w};

    float sx[4], sy[4], xlo[4], xhi[4], ylo[4], yhi[4], nap[4];
    #pragma unroll
    for (int c = 0; c < 4; c++) {
        sx[c] = sig_fast(X[c]);
        sy[c] = sig_fast(Y[c]);
        float pw = __expf(W[c]) * aw_;
        float pl = __expf(L[c]) * ah_;
        float hpw = 0.5f * pw;
        float hpl = 0.5f * pl;
        float px = sx[c] + (float)(w0 + c);
        float py = sy[c] + (float)h;
        xlo[c] = px - hpw;
        xhi[c] = px + hpw;
        ylo[c] = py - hpl;
        yhi[c] = py + hpl;
        nap[c] = -THRESH_Q * pw * pl;
    }

    bool f0 = false, f1 = false, f2 = false, f3 = false;

    #pragma unroll 10
    for (int t = 0; t < NT; t++) {
        const float4 bx = s_box[t];   // {xlo, xhi, ylo, yhi}
        const float  th = s_thr[t];
        // single clamp on cw suffices: product > th (>0) requires ch > 0 too;
        // cw<=0 gives 0 or NaN product, both fail the compare.
        {
            float cwc = fmaxf(fminf(xhi[0], bx.y) - fmaxf(xlo[0], bx.x), 0.0f);
            float ch  = fminf(yhi[0], bx.w) - fmaxf(ylo[0], bx.z);
            f0 = f0 | (fmaf(cwc, ch, nap[0]) > th);
        }
        {
            float cwc = fmaxf(fminf(xhi[1], bx.y) - fmaxf(xlo[1], bx.x), 0.0f);
            float ch  = fminf(yhi[1], bx.w) - fmaxf(ylo[1], bx.z);
            f1 = f1 | (fmaf(cwc, ch, nap[1]) > th);
        }
        {
            float cwc = fmaxf(fminf(xhi[2], bx.y) - fmaxf(xlo[2], bx.x), 0.0f);
            float ch  = fminf(yhi[2], bx.w) - fmaxf(ylo[2], bx.z);
            f2 = f2 | (fmaf(cwc, ch, nap[2]) > th);
        }
        {
            float cwc = fmaxf(fminf(xhi[3], bx.y) - fmaxf(xlo[3], bx.x), 0.0f);
            float ch  = fminf(yhi[3], bx.w) - fmaxf(ylo[3], bx.z);
            f3 = f3 | (fmaf(cwc, ch, nap[3]) > th);
        }
    }

    const float CF[4] = {cfr.x, cfr.y, cfr.z, cfr.w};
    const unsigned char MK[4] = {mk.x, mk.y, mk.z, mk.w};
    const bool F[4] = {f0, f1, f2, f3};

    float part = 0.0f;
    #pragma unroll
    for (int c = 0; c < 4; c++) {
        float cf = sig_fast(CF[c]);
        if (MK[c]) {
            part += target_terms(b * NT + (MK[c] - 1), sx[c], sy[c], W[c], L[c], cf, base, c);
        } else if (!F[c]) {
            part += cf * cf;   // no-obj conf term
        }
    }

    // block reduction (warp shuffle + smem), one global store per block
    const int lane = tid & 31, warp = tid >> 5;
    #pragma unroll
    for (int off = 16; off > 0; off >>= 1)
        part += __shfl_down_sync(0xffffffffu, part, off);
    __shared__ float s_red[8];
    if (lane == 0) s_red[warp] = part;
    __syncthreads();
    if (tid == 0) {
        float v = 0.f;
        #pragma unroll
        for (int wv = 0; wv < 8; wv++) v += s_red[wv];
        g_part[b * BLKS_PER_B + blockIdx.x] = v;
    }
}

// -------------------- kernel 3: finalize + restore g_match -------------------
__global__ void k_fin(float* __restrict__ o, int n) {
    const int tid = threadIdx.x;

    // restore g_match to all-zero for the next invocation
    if (tid < NBT) {
        int w = g_widx[tid];
        if (w >= 0) g_match[w] = 0;
    }

    double s = 0.0;
    for (int i = tid; i < NBLK; i += 1024) s += (double)g_part[i];

    const int lane = tid & 31, warp = tid >> 5;
    #pragma unroll
    for (int off = 16; off > 0; off >>= 1)
        s += __shfl_down_sync(0xffffffffu, s, off);
    __shared__ double sd[32];
    if (lane == 0) sd[warp] = s;
    __syncthreads();
    if (warp == 0) {
        double v = sd[lane];
        #pragma unroll
        for (int off = 16; off > 0; off >>= 1)
            v += __shfl_down_sync(0xffffffffu, v, off);
        if (tid == 0) {
            int gt = 0, cc = 0;
            #pragma unroll
            for (int i = 0; i < NB; i++) { gt += g_cntGT[i]; cc += g_cntCor[i]; }
            if (n > 0) o[0] = (float)v;
            if (n > 1) o[1] = (float)cc;
            if (n > 2) o[2] = (float)gt;
        }
    }
    for (int k = 3 + tid; k < n; k += 1024) o[k] = 0.0f;
}

// -------------------- launch --------------------------------------------------
extern "C" void kernel_launch(void* const* d_in, const int* in_sizes, int n_in,
                              void* d_out, int out_size) {
    const float* output  = (const float*)d_in[0];
    const float* target  = (const float*)d_in[1];
    const float* anchors = (const float*)d_in[2];

    k_targets<<<NB, 64>>>(output, target, anchors);
    k_main<<<dim3(BLKS_PER_B, NB), 256>>>(output, anchors);
    k_fin<<<1, 1024>>>((float*)d_out, out_size);
}